// round 9
// baseline (speedup 1.0000x reference)
#include <cuda_runtime.h>
#include <cuda_bf16.h>
#include <cstdint>

using bf16 = __nv_bfloat16;

#define HW    4096
#define DCH   256

// ---------------- static device scratch (no allocations) ----------------
__device__ bf16  g_xln[2*DCH*HW];   // LN(image) bf16 [b][c][p]
__device__ bf16  g_gln[2*DCH*HW];   // LN(guide) bf16 [b][c][p]
__device__ float g_buf[2*DCH*HW];   // conv1x1 output fp32 [b][c][p]
__device__ bf16  g_qT[2*DCH*HW];    // [bh][p][hd]
__device__ bf16  g_kT[2*DCH*HW];
__device__ bf16  g_vT[2*DCH*HW];
__device__ bf16  g_xo[2*DCH*HW];    // attention output bf16 [b][c][p]

// ---------------- helpers ----------------
__device__ __forceinline__ uint32_t smem_u32(const void* p){
    return (uint32_t)__cvta_generic_to_shared(p);
}
__device__ __forceinline__ void ldsm_x4(uint32_t &r0,uint32_t &r1,uint32_t &r2,uint32_t &r3,uint32_t a){
    asm volatile("ldmatrix.sync.aligned.m8n8.x4.shared.b16 {%0,%1,%2,%3},[%4];"
      : "=r"(r0),"=r"(r1),"=r"(r2),"=r"(r3) : "r"(a));
}
__device__ __forceinline__ void ldsm_x4t(uint32_t &r0,uint32_t &r1,uint32_t &r2,uint32_t &r3,uint32_t a){
    asm volatile("ldmatrix.sync.aligned.m8n8.x4.trans.shared.b16 {%0,%1,%2,%3},[%4];"
      : "=r"(r0),"=r"(r1),"=r"(r2),"=r"(r3) : "r"(a));
}
__device__ __forceinline__ void mma16816(float* c, const uint32_t* a, const uint32_t* b){
    asm volatile("mma.sync.aligned.m16n8k16.row.col.f32.bf16.bf16.f32 "
      "{%0,%1,%2,%3},{%4,%5,%6,%7},{%8,%9},{%0,%1,%2,%3};"
      : "+f"(c[0]),"+f"(c[1]),"+f"(c[2]),"+f"(c[3])
      : "r"(a[0]),"r"(a[1]),"r"(a[2]),"r"(a[3]),"r"(b[0]),"r"(b[1]));
}
__device__ __forceinline__ float ex2f(float x){
    float y; asm("ex2.approx.f32 %0,%1;" : "=f"(y) : "f"(x)); return y;
}
__device__ __forceinline__ uint32_t packbf2(float lo, float hi){
    __nv_bfloat162 v = __floats2bfloat162_rn(lo, hi);
    return *reinterpret_cast<uint32_t*>(&v);
}

// ---------------- 1) LayerNorm over channels -> bf16 ----------------
__global__ __launch_bounds__(256) void ln_kernel(
    const float* __restrict__ img, const float* __restrict__ gde,
    const float* __restrict__ g1,  const float* __restrict__ b1,
    const float* __restrict__ g2,  const float* __restrict__ b2)
{
    int which = blockIdx.y;
    const float* x  = which ? gde : img;
    const float* gg = which ? g2  : g1;
    const float* bb = which ? b2  : b1;
    bf16* y = which ? g_gln : g_xln;

    int tx = threadIdx.x, ty = threadIdx.y;       // (32, 8)
    int p = blockIdx.x*32 + tx;                   // 0..8191 = b*HW + pin
    int b = p >> 12, pin = p & 4095;
    const float* xb = x + ((size_t)b*DCH)*HW + pin;

    float s = 0.f, sq = 0.f;
    for (int c = ty; c < DCH; c += 8){
        float v = xb[(size_t)c*HW];
        s += v; sq += v*v;
    }
    __shared__ float ps[8][32], pq[8][32], mS[32], rS[32];
    ps[ty][tx] = s; pq[ty][tx] = sq;
    __syncthreads();
    if (ty == 0){
        float S = 0.f, Q = 0.f;
        #pragma unroll
        for (int j = 0; j < 8; j++){ S += ps[j][tx]; Q += pq[j][tx]; }
        float mean = S * (1.f/256.f);
        float var  = Q * (1.f/256.f) - mean*mean;
        mS[tx] = mean;
        rS[tx] = rsqrtf(var + 1e-5f);
    }
    __syncthreads();
    float mean = mS[tx], rstd = rS[tx];
    bf16* yb = y + ((size_t)b*DCH)*HW + pin;
    for (int c = ty; c < DCH; c += 8)
        yb[(size_t)c*HW] = __float2bfloat16((xb[(size_t)c*HW]-mean)*rstd*gg[c] + bb[c]);
}

// ---------------- 2) conv1x1 as bf16 mma GEMM ----------------
// Y[b][o][p] = sum_c W[o][c] * X[b][c][p] + bias[o]  (+ residual)
// xsel: 0 = g_xln, 1 = g_gln, 2 = g_xo.  Yext==null -> g_buf.
__global__ __launch_bounds__(256) void gemm_kernel(
    const float* __restrict__ W, const float* __restrict__ bias,
    int xsel, float* __restrict__ Yext, const float* __restrict__ res)
{
    const bf16* X = (xsel==0) ? g_xln : (xsel==1) ? g_gln : g_xo;
    float* Y = Yext ? Yext : g_buf;

    __shared__ bf16 sA[128*40];     // W tile [128 m][32 k], stride 40
    __shared__ bf16 sB[32*136];     // X tile [32 k][128 n], stride 136
    int tid = threadIdx.x, lane = tid & 31, wid = tid >> 5;
    int wm = (wid & 1) * 64, wn = (wid >> 1) * 32;
    int b = blockIdx.z, m0 = blockIdx.y*128, n0 = blockIdx.x*128;
    const bf16* Xb = X + (size_t)b*DCH*HW;

    float acc[4][4][4];
    #pragma unroll
    for (int i=0;i<4;i++)
      #pragma unroll
      for (int j=0;j<4;j++){ acc[i][j][0]=0.f; acc[i][j][1]=0.f; acc[i][j][2]=0.f; acc[i][j][3]=0.f; }

    for (int kt = 0; kt < 8; kt++){
        int c0 = kt*32;
        #pragma unroll
        for (int pass = 0; pass < 4; pass++){          // A: fp32 -> bf16 on the fly
            int r = (tid>>3) + pass*32, col = (tid&7)*4;
            float4 wv = *(const float4*)&W[(m0+r)*DCH + c0 + col];
            uint2 pk; pk.x = packbf2(wv.x, wv.y); pk.y = packbf2(wv.z, wv.w);
            *(uint2*)&sA[r*40 + col] = pk;
        }
        #pragma unroll
        for (int pass = 0; pass < 2; pass++){          // B
            int r = (tid>>4) + pass*16, ch = (tid&15)*8;
            *(uint4*)&sB[r*136 + ch] = *(const uint4*)&Xb[(size_t)(c0+r)*HW + n0 + ch];
        }
        __syncthreads();
        #pragma unroll
        for (int kk = 0; kk < 2; kk++){
            uint32_t a[4][4], bf[4][2];
            #pragma unroll
            for (int mi = 0; mi < 4; mi++){
                uint32_t ad = smem_u32(&sA[(wm+mi*16+(lane&15))*40 + kk*16 + ((lane>>4)<<3)]);
                ldsm_x4(a[mi][0],a[mi][1],a[mi][2],a[mi][3], ad);
            }
            #pragma unroll
            for (int jp = 0; jp < 2; jp++){
                uint32_t ad = smem_u32(&sB[(kk*16+(lane&15))*136 + wn + jp*16 + (((lane>>4)&1)<<3)]);
                ldsm_x4t(bf[2*jp][0],bf[2*jp][1],bf[2*jp+1][0],bf[2*jp+1][1], ad);
            }
            #pragma unroll
            for (int mi = 0; mi < 4; mi++)
                #pragma unroll
                for (int ni = 0; ni < 4; ni++)
                    mma16816(acc[mi][ni], a[mi], bf[ni]);
        }
        __syncthreads();
    }
    #pragma unroll
    for (int mi = 0; mi < 4; mi++){
        int r0 = m0 + wm + mi*16 + (lane>>2);
        float b0v = bias[r0], b1v = bias[r0+8];
        #pragma unroll
        for (int ni = 0; ni < 4; ni++){
            int c = n0 + wn + ni*8 + ((lane&3)<<1);
            size_t i0 = ((size_t)b*DCH + r0)*HW + c;
            size_t i1 = i0 + (size_t)8*HW;
            float2 v0 = make_float2(acc[mi][ni][0]+b0v, acc[mi][ni][1]+b0v);
            float2 v1 = make_float2(acc[mi][ni][2]+b1v, acc[mi][ni][3]+b1v);
            if (res){
                v0.x += res[i0]; v0.y += res[i0+1];
                v1.x += res[i1]; v1.y += res[i1+1];
            }
            *(float2*)&Y[i0] = v0;
            *(float2*)&Y[i1] = v1;
        }
    }
}

// ---------------- 3) depthwise 3x3 + bias + scale + head transpose ----------------
// in: g_buf fp32 [b][c][64][64]; out: [bh][p][hd] bf16 (osel: 0=q,1=k,2=v)
__global__ __launch_bounds__(256) void dwconv_kernel(
    const float* __restrict__ w, const float* __restrict__ bias,
    int osel, float scale)
{
    __shared__ bf16 sT[256*66];
    int b = blockIdx.z, h = blockIdx.y, pt = blockIdx.x;
    int tid = threadIdx.x;
    int p = pt*256 + tid;
    int y = p >> 6, x = p & 63;
    bf16* out = (osel==0) ? g_qT : (osel==1) ? g_kT : g_vT;

    #pragma unroll 1
    for (int d = 0; d < 64; d++){
        int c = h*64 + d;
        const float* ip = g_buf + ((size_t)b*DCH + c)*HW;
        const float* wp = w + c*9;
        float acc = bias[c];
        #pragma unroll
        for (int dy = -1; dy <= 1; dy++){
            int yy = y + dy;
            if ((unsigned)yy < 64u){
                #pragma unroll
                for (int dx = -1; dx <= 1; dx++){
                    int xx = x + dx;
                    if ((unsigned)xx < 64u)
                        acc += wp[(dy+1)*3+(dx+1)] * __ldg(&ip[yy*64+xx]);
                }
            }
        }
        sT[tid*66 + d] = __float2bfloat16(acc*scale);
    }
    __syncthreads();
    bf16* op = out + (((size_t)b*4 + h)*HW + pt*256)*64;
    for (int i = tid; i < 256*32; i += 256){
        int pp = i >> 5, d2 = i & 31;
        *(uint32_t*)&op[pp*64 + d2*2] = *(uint32_t*)&sT[pp*66 + d2*2];
    }
}

// ---------------- 4) flash attention (bf16 mma.sync, base-2 online softmax) ----------------
#define QSTR 72
__global__ __launch_bounds__(256) void attn_kernel()
{
    __shared__ bf16 sQ[128*QSTR];
    __shared__ bf16 sK[64*QSTR];
    __shared__ bf16 sV[64*QSTR];
    int tid = threadIdx.x, lane = tid & 31, wid = tid >> 5;
    int bh = blockIdx.y;
    int q0 = blockIdx.x * 128;
    const bf16* Qp = g_qT + ((size_t)bh*HW + q0)*64;
    const bf16* Kp = g_kT + (size_t)bh*HW*64;
    const bf16* Vp = g_vT + (size_t)bh*HW*64;

    #pragma unroll
    for (int pass = 0; pass < 4; pass++){
        int r = (tid>>3) + pass*32, ch = (tid&7)*8;
        *(uint4*)&sQ[r*QSTR + ch] = *(const uint4*)&Qp[(size_t)r*64 + ch];
    }
    __syncthreads();

    int mw = wid*16;                       // 16 query rows per warp
    uint32_t aq[4][4];                     // Q fragments stay in registers
    #pragma unroll
    for (int kk = 0; kk < 4; kk++){
        uint32_t ad = smem_u32(&sQ[(mw+(lane&15))*QSTR + kk*16 + ((lane>>4)<<3)]);
        ldsm_x4(aq[kk][0],aq[kk][1],aq[kk][2],aq[kk][3], ad);
    }

    float m0 = -1e30f, m1 = -1e30f, l0 = 0.f, l1 = 0.f;
    float o[8][4];
    #pragma unroll
    for (int j = 0; j < 8; j++){ o[j][0]=0.f; o[j][1]=0.f; o[j][2]=0.f; o[j][3]=0.f; }

    for (int kb = 0; kb < 64; kb++){
        __syncthreads();
        const bf16* kp = Kp + (size_t)kb*64*64;
        const bf16* vp = Vp + (size_t)kb*64*64;
        #pragma unroll
        for (int pass = 0; pass < 2; pass++){
            int r = (tid>>3) + pass*32, ch = (tid&7)*8;
            *(uint4*)&sK[r*QSTR+ch] = *(const uint4*)&kp[r*64+ch];
            *(uint4*)&sV[r*QSTR+ch] = *(const uint4*)&vp[r*64+ch];
        }
        __syncthreads();

        // S = Q K^T  (16 x 64 per warp)
        float s[8][4];
        #pragma unroll
        for (int j = 0; j < 8; j++){ s[j][0]=0.f; s[j][1]=0.f; s[j][2]=0.f; s[j][3]=0.f; }
        #pragma unroll
        for (int kk = 0; kk < 4; kk++){
            uint32_t bk[8][2];
            #pragma unroll
            for (int jp = 0; jp < 4; jp++){
                uint32_t ad = smem_u32(&sK[(jp*16 + ((lane>>4)<<3) + (lane&7))*QSTR
                                           + kk*16 + (((lane>>3)&1)<<3)]);
                ldsm_x4(bk[2*jp][0],bk[2*jp][1],bk[2*jp+1][0],bk[2*jp+1][1], ad);
            }
            #pragma unroll
            for (int j = 0; j < 8; j++) mma16816(s[j], aq[kk], bk[j]);
        }

        // online softmax (base-2; log2e folded into q)
        float mx0 = -1e30f, mx1 = -1e30f;
        #pragma unroll
        for (int j = 0; j < 8; j++){
            mx0 = fmaxf(mx0, fmaxf(s[j][0], s[j][1]));
            mx1 = fmaxf(mx1, fmaxf(s[j][2], s[j][3]));
        }
        mx0 = fmaxf(mx0, __shfl_xor_sync(0xffffffffu, mx0, 1));
        mx0 = fmaxf(mx0, __shfl_xor_sync(0xffffffffu, mx0, 2));
        mx1 = fmaxf(mx1, __shfl_xor_sync(0xffffffffu, mx1, 1));
        mx1 = fmaxf(mx1, __shfl_xor_sync(0xffffffffu, mx1, 2));
        float nm0 = fmaxf(m0, mx0), nm1 = fmaxf(m1, mx1);
        float al0 = ex2f(m0 - nm0), al1 = ex2f(m1 - nm1);
        m0 = nm0; m1 = nm1;
        float rs0 = 0.f, rs1 = 0.f;
        uint32_t pa[8][2];
        #pragma unroll
        for (int j = 0; j < 8; j++){
            float p0 = ex2f(s[j][0]-nm0), p1 = ex2f(s[j][1]-nm0);
            float p2 = ex2f(s[j][2]-nm1), p3 = ex2f(s[j][3]-nm1);
            rs0 += p0 + p1; rs1 += p2 + p3;
            pa[j][0] = packbf2(p0, p1);
            pa[j][1] = packbf2(p2, p3);
        }
        rs0 += __shfl_xor_sync(0xffffffffu, rs0, 1);
        rs0 += __shfl_xor_sync(0xffffffffu, rs0, 2);
        rs1 += __shfl_xor_sync(0xffffffffu, rs1, 1);
        rs1 += __shfl_xor_sync(0xffffffffu, rs1, 2);
        l0 = l0*al0 + rs0; l1 = l1*al1 + rs1;
        #pragma unroll
        for (int j = 0; j < 8; j++){ o[j][0]*=al0; o[j][1]*=al0; o[j][2]*=al1; o[j][3]*=al1; }

        // O += P V  (P fragments are a pure per-thread repack of S fragments)
        #pragma unroll
        for (int kk = 0; kk < 4; kk++){
            uint32_t av[4] = { pa[2*kk][0], pa[2*kk][1], pa[2*kk+1][0], pa[2*kk+1][1] };
            uint32_t bv[8][2];
            #pragma unroll
            for (int jp = 0; jp < 4; jp++){
                uint32_t ad = smem_u32(&sV[(kk*16 + (lane&15))*QSTR
                                           + jp*16 + (((lane>>4)&1)<<3)]);
                ldsm_x4t(bv[2*jp][0],bv[2*jp][1],bv[2*jp+1][0],bv[2*jp+1][1], ad);
            }
            #pragma unroll
            for (int j = 0; j < 8; j++) mma16816(o[j], av, bv[j]);
        }
    }

    // normalize, transpose via smem (reuse sQ), write [b][c][p]
    float il0 = 1.f/l0, il1 = 1.f/l1;
    __syncthreads();
    #pragma unroll
    for (int j = 0; j < 8; j++){
        int r = mw + (lane>>2), c = j*8 + ((lane&3)<<1);
        *(uint32_t*)&sQ[r*QSTR + c]       = packbf2(o[j][0]*il0, o[j][1]*il0);
        *(uint32_t*)&sQ[(r+8)*QSTR + c]   = packbf2(o[j][2]*il1, o[j][3]*il1);
    }
    __syncthreads();
    int b = bh >> 2, h = bh & 3;
    bf16* op = g_xo + ((size_t)b*DCH + h*64)*HW + q0;
    for (int i = tid; i < 64*128; i += 256){
        int d = i >> 7, p = i & 127;
        op[(size_t)d*HW + p] = sQ[p*QSTR + d];
    }
}

// ---------------- launch ----------------
extern "C" void kernel_launch(void* const* d_in, const int* in_sizes, int n_in,
                              void* d_out, int out_size)
{
    const float* img  = (const float*)d_in[0];
    const float* gde  = (const float*)d_in[1];
    const float* ln1g = (const float*)d_in[2];
    const float* ln1b = (const float*)d_in[3];
    const float* ln2g = (const float*)d_in[4];
    const float* ln2b = (const float*)d_in[5];
    const float* qw1  = (const float*)d_in[6];
    const float* qb1  = (const float*)d_in[7];
    const float* qw2  = (const float*)d_in[8];
    const float* qb2  = (const float*)d_in[9];
    const float* kw1  = (const float*)d_in[10];
    const float* kb1  = (const float*)d_in[11];
    const float* kw2  = (const float*)d_in[12];
    const float* kb2  = (const float*)d_in[13];
    const float* vw1  = (const float*)d_in[14];
    const float* vb1  = (const float*)d_in[15];
    const float* vw2  = (const float*)d_in[16];
    const float* vb2  = (const float*)d_in[17];
    const float* ow   = (const float*)d_in[18];
    const float* ob   = (const float*)d_in[19];
    float* out = (float*)d_out;

    ln_kernel<<<dim3(256,2), dim3(32,8)>>>(img, gde, ln1g, ln1b, ln2g, ln2b);

    dim3 gg(32,2,2);
    const float qscale = 0.125f * 1.44269504088896340736f;  // hd^-0.5 * log2(e)

    gemm_kernel<<<gg, 256>>>(qw1, qb1, 0, nullptr, nullptr);
    dwconv_kernel<<<dim3(16,4,2), 256>>>(qw2, qb2, 0, qscale);

    gemm_kernel<<<gg, 256>>>(kw1, kb1, 1, nullptr, nullptr);
    dwconv_kernel<<<dim3(16,4,2), 256>>>(kw2, kb2, 1, 1.0f);

    gemm_kernel<<<gg, 256>>>(vw1, vb1, 1, nullptr, nullptr);
    dwconv_kernel<<<dim3(16,4,2), 256>>>(vw2, vb2, 2, 1.0f);

    attn_kernel<<<dim3(32,8), 256>>>();

    gemm_kernel<<<gg, 256>>>(ow, ob, 2, out, img);
}